// round 2
// baseline (speedup 1.0000x reference)
#include <cuda_runtime.h>
#include <cuda_bf16.h>

#define N_GRAPHS 1024
#define D_FEAT   128
#define HID      16
#define RPB      1024   // rows per block in phase A

// Scratch accumulators (per-graph). Zeroed every launch for determinism.
__device__ float g_fsum[N_GRAPHS * D_FEAT];   // segment-sum of x
__device__ float g_asum[N_GRAPHS * HID];      // segment-sum of relu(cp*W1+b1)
__device__ float g_cnt [N_GRAPHS];            // segment counts

// ---------------------------------------------------------------------------
// Kernel 0: zero the accumulators
// ---------------------------------------------------------------------------
__global__ void zero_kernel() {
    int i = blockIdx.x * blockDim.x + threadIdx.x;
    if (i < N_GRAPHS * D_FEAT) g_fsum[i] = 0.f;
    if (i < N_GRAPHS * HID)    g_asum[i] = 0.f;
    if (i < N_GRAPHS)          g_cnt[i]  = 0.f;
}

// ---------------------------------------------------------------------------
// Phase A: stream x once. One warp per row (lane l owns features [4l,4l+4)).
// batch is sorted, so each warp keeps a register accumulator for its current
// segment and flushes with atomics only when the segment id changes (or at
// chunk end). Also accumulates a = relu(cp*W1+b1) on lanes 0..15 (the @W2
// and +b2 are linear and applied after pooling in the finalize kernel).
// ---------------------------------------------------------------------------
__device__ __forceinline__ void flush_seg(int g, int lane, const float4& acc,
                                          float aacc, float run) {
    float* p = g_fsum + g * D_FEAT + lane * 4;
    atomicAdd(p + 0, acc.x);
    atomicAdd(p + 1, acc.y);
    atomicAdd(p + 2, acc.z);
    atomicAdd(p + 3, acc.w);
    if (lane < HID) atomicAdd(g_asum + g * HID + lane, aacc);
    if (lane == 0)  atomicAdd(g_cnt + g, run);
}

__global__ void __launch_bounds__(256) phaseA_kernel(
    const float4* __restrict__ x4,       // [N, 32] float4 view of [N,128]
    const float*  __restrict__ cp,       // [N]
    const int*    __restrict__ batch,    // [N] sorted
    const float*  __restrict__ W1,       // [16]
    const float*  __restrict__ b1,       // [16]
    int n)
{
    const int warp = threadIdx.x >> 5;
    const int lane = threadIdx.x & 31;
    const int start = blockIdx.x * RPB;
    const int end   = min(start + RPB, n);

    const float w1v = (lane < HID) ? __ldg(W1 + lane) : 0.f;
    const float b1v = (lane < HID) ? __ldg(b1 + lane) : 0.f;

    float4 acc = make_float4(0.f, 0.f, 0.f, 0.f);
    float  aacc = 0.f;
    float  run  = 0.f;
    int    cur  = -1;

    // 8 warps/block; each warp covers rows start+warp, +8, +16, ...
    // Quad-unrolled so 4 independent LDG.128 are in flight per lane.
    for (int base = start + warp; base < end; base += 32) {
        int    gs[4];
        float4 vs[4];
        float  cs[4];
        bool   ok[4];
#pragma unroll
        for (int q = 0; q < 4; q++) {
            int r = base + q * 8;
            ok[q] = (r < end);          // warp-uniform predicate (r same on all lanes)
            if (ok[q]) {
                gs[q] = __ldg(batch + r);
                vs[q] = __ldg(x4 + (long)r * 32 + lane);
                cs[q] = __ldg(cp + r);
            }
        }
#pragma unroll
        for (int q = 0; q < 4; q++) {
            if (!ok[q]) continue;       // warp-uniform
            int g = gs[q];
            if (g != cur) {             // rare: ~2 boundary events per warp per chunk
                if (run > 0.f) flush_seg(cur, lane, acc, aacc, run);
                cur = g;
                acc = make_float4(0.f, 0.f, 0.f, 0.f);
                aacc = 0.f;
                run = 0.f;
            }
            acc.x += vs[q].x; acc.y += vs[q].y;
            acc.z += vs[q].z; acc.w += vs[q].w;
            aacc += fmaxf(fmaf(cs[q], w1v, b1v), 0.f);
            run += 1.f;
        }
    }
    if (run > 0.f) flush_seg(cur, lane, acc, aacc, run);
}

// ---------------------------------------------------------------------------
// Finalize: one warp (block of 32) per graph.
//   graph_pred = (sum_f / cnt) . W_base + b_base
//   clock_pool = (a_sum / cnt) @ W2 + b2
//   combined[17] -> relu(@W3 + b3)[32] -> @W4 + b4 -> out[g]
// ---------------------------------------------------------------------------
__global__ void __launch_bounds__(32) finalize_kernel(
    const float* __restrict__ Wb,  const float* __restrict__ bb,
    const float* __restrict__ W2,  const float* __restrict__ b2,
    const float* __restrict__ W3,  const float* __restrict__ b3,
    const float* __restrict__ W4,  const float* __restrict__ b4,
    float* __restrict__ out)
{
    const int g    = blockIdx.x;
    const int lane = threadIdx.x;

    const float cnt = fmaxf(g_cnt[g], 1.f);
    const float inv = 1.f / cnt;

    // graph_pred: dot(sum_f, W_base) via warp reduce
    float d = 0.f;
#pragma unroll
    for (int k = 0; k < 4; k++) {
        int f = lane * 4 + k;
        d += g_fsum[g * D_FEAT + f] * __ldg(Wb + f);
    }
#pragma unroll
    for (int o = 16; o > 0; o >>= 1) d += __shfl_xor_sync(0xFFFFFFFFu, d, o);
    const float graph_pred = d * inv + __ldg(bb);

    __shared__ float c[HID + 1];
    if (lane == 0) c[0] = graph_pred;
    if (lane < HID) {
        float s = 0.f;
#pragma unroll
        for (int i = 0; i < HID; i++)
            s += g_asum[g * HID + i] * __ldg(W2 + i * HID + lane);
        c[1 + lane] = s * inv + __ldg(b2 + lane);
    }
    __syncwarp();

    // z_k = relu(sum_m c[m] * W3[m][k] + b3[k]),  k = lane (32 lanes, 32 cols)
    float z = __ldg(b3 + lane);
#pragma unroll
    for (int m = 0; m < HID + 1; m++)
        z = fmaf(c[m], __ldg(W3 + m * 32 + lane), z);
    z = fmaxf(z, 0.f);

    float o2 = z * __ldg(W4 + lane);
#pragma unroll
    for (int o = 16; o > 0; o >>= 1) o2 += __shfl_xor_sync(0xFFFFFFFFu, o2, o);
    if (lane == 0) out[g] = o2 + __ldg(b4);
}

// ---------------------------------------------------------------------------
// Launch
// ---------------------------------------------------------------------------
extern "C" void kernel_launch(void* const* d_in, const int* in_sizes, int n_in,
                              void* d_out, int out_size)
{
    const float* x    = (const float*)d_in[0];
    const float* cp   = (const float*)d_in[1];
    const int*   bat  = (const int*)  d_in[2];
    const float* Wb   = (const float*)d_in[3];
    const float* bb   = (const float*)d_in[4];
    const float* W1   = (const float*)d_in[5];
    const float* b1   = (const float*)d_in[6];
    const float* W2   = (const float*)d_in[7];
    const float* b2   = (const float*)d_in[8];
    const float* W3   = (const float*)d_in[9];
    const float* b3   = (const float*)d_in[10];
    const float* W4   = (const float*)d_in[11];
    const float* b4   = (const float*)d_in[12];
    float* out = (float*)d_out;

    int n = in_sizes[2];   // N_NODES (batch element count)
    if (n < 0) n = 0;

    {
        int tot = N_GRAPHS * D_FEAT;  // largest accumulator; zero_kernel guards rest
        int blocks = (tot + 255) / 256;
        zero_kernel<<<blocks, 256>>>();
    }
    if (n > 0) {
        int blocks = (n + RPB - 1) / RPB;
        phaseA_kernel<<<blocks, 256>>>((const float4*)x, cp, bat, W1, b1, n);
    }
    finalize_kernel<<<N_GRAPHS, 32>>>(Wb, bb, W2, b2, W3, b3, W4, b4, out);
}